// round 17
// baseline (speedup 1.0000x reference)
#include <cuda_runtime.h>
#include <cuda_bf16.h>
#include <cstdint>

// Volume rendering composite.
// Inputs: depth [N,192,1] f32, rgb [N,192,3] f32, sigma [N,192,1] f32
// Output (concat, f32): color [N,3], depth_out [N,1], acc_map [N,1], weights [N,192,1]
//
// One warp per ray (R15 structure — best measured: ncu 42.88us, DRAM 83.3%):
//  - rgb (60% of read bytes) prefetched FIRST via cp.async.cg into per-warp
//    smem: traffic overlaps the scan phase; no registers held; L1 bypassed.
//  - depth/sigma: direct LDG.128/LDG.64 into registers (lowest-latency path).
//  - transmittance: 2 chained 5-step warp scans; -log2e folded into sigma.
//  - weights: direct coalesced STG.128 + STG.64 from registers.
//  - rgb consume: compile-time component swizzle from smem.
//  - THIS ROUND'S single variable: launch_bounds (256,7) -> (256,8). The
//    binary is already at 32 regs, so the cap is unchanged and the schedule
//    should be identical; this only raises max resident blocks 7 -> 8
//    (56 -> 64 warps/SM; smem 147KB and RF 64K both fit exactly).

#define NRAYS 65536
#define NSAMP 192
#define WPB   8
#define RGBF  (NSAMP * 3)   // 576 floats per ray

__device__ __forceinline__ float ex2_approx(float x) {
    float r; asm("ex2.approx.f32 %0, %1;" : "=f"(r) : "f"(x)); return r;
}
__device__ __forceinline__ float tanh_approx(float x) {
    float r; asm("tanh.approx.f32 %0, %1;" : "=f"(r) : "f"(x)); return r;
}
// sigmoid(x) = 0.5*tanh(x/2) + 0.5  (one MUFU op)
__device__ __forceinline__ float sigmoid_fast(float x) {
    return fmaf(0.5f, tanh_approx(0.5f * x), 0.5f);
}
__device__ __forceinline__ uint32_t smem_u32(const void* p) {
    uint32_t a;
    asm("{ .reg .u64 t; cvta.to.shared.u64 t, %1; cvt.u32.u64 %0, t; }"
        : "=r"(a) : "l"(p));
    return a;
}

__global__ void __launch_bounds__(256, 8)
volrend_kernel(const float* __restrict__ depth,
               const float* __restrict__ rgb,
               const float* __restrict__ sigma,
               float* __restrict__ out)
{
    const int wid  = threadIdx.x >> 5;
    const int lane = threadIdx.x & 31;
    const int ray  = blockIdx.x * WPB + wid;

    __shared__ __align__(16) float srgb[WPB][RGBF];   // 18.4 KB/block

    const float BOARDER = 1e10f;
    const float EPS     = 1e-10f;
    const float NLOG2E  = -1.4426950408889634f;
    const unsigned FULL = 0xffffffffu;

    // ---- 1) rgb prefetch: cp.async.cg, issued before ANY compute ----
    const char* rsrc = (const char*)(rgb + (size_t)ray * RGBF);
    const uint32_t rdst = smem_u32(&srgb[wid][0]);
    #pragma unroll
    for (int t = 0; t < 4; ++t) {
        asm volatile("cp.async.cg.shared.global [%0], [%1], 16;\n" ::
                     "r"(rdst + (32 * t + lane) * 16),
                     "l"(rsrc + (32 * t + lane) * 16));
    }
    // tail 256B: 16 lanes x 16B, .cg (no L1 pollution)
    if (lane < 16) {
        asm volatile("cp.async.cg.shared.global [%0], [%1], 16;\n" ::
                     "r"(rdst + 2048 + lane * 16),
                     "l"(rsrc + 2048 + lane * 16));
    }
    asm volatile("cp.async.commit_group;\n");

    // ---- 2) depth/sigma loads (coalesced 128/64-bit, straight to regs) ----
    const float* dbase = depth + (size_t)ray * NSAMP;
    const float* gbase = sigma + (size_t)ray * NSAMP;
    const float4 dA = __ldcs((const float4*)dbase + lane);          // 4l..4l+3
    const float2 dB = __ldcs((const float2*)(dbase + 128) + lane);  // 128+2l..+1
    const float4 gA = __ldcs((const float4*)gbase + lane);
    const float2 gB = __ldcs((const float2*)(gbase + 128) + lane);

    // next-sample depths across lane boundaries
    float ndA = __shfl_down_sync(FULL, dA.x, 1);
    const float bA = __shfl_sync(FULL, dB.x, 0);       // d[128]
    if (lane == 31) ndA = bA;
    const float ndB = __shfl_down_sync(FULL, dB.x, 1); // d[128+2l+2]

    // ---- 3) chunk A: 4 survivals, warp product-scan ----
    // fold -log2e into the relu'd sigma: e = ex2(gs * delta)
    const float gsA0 = fmaxf(gA.x, 0.f) * NLOG2E;
    const float gsA1 = fmaxf(gA.y, 0.f) * NLOG2E;
    const float gsA2 = fmaxf(gA.z, 0.f) * NLOG2E;
    const float gsA3 = fmaxf(gA.w, 0.f) * NLOG2E;
    const float eA0 = ex2_approx(gsA0 * (dA.y - dA.x));
    const float eA1 = ex2_approx(gsA1 * (dA.z - dA.y));
    const float eA2 = ex2_approx(gsA2 * (dA.w - dA.z));
    const float eA3 = ex2_approx(gsA3 * (ndA  - dA.w));
    const float sA0 = eA0 + EPS, sA1 = eA1 + EPS, sA2 = eA2 + EPS, sA3 = eA3 + EPS;

    float inclA = (sA0 * sA1) * (sA2 * sA3);
    #pragma unroll
    for (int off = 1; off < 32; off <<= 1) {
        const float v = __shfl_up_sync(FULL, inclA, off);
        if (lane >= off) inclA *= v;
    }
    float exclA = __shfl_up_sync(FULL, inclA, 1);
    if (lane == 0) exclA = 1.0f;

    float T = exclA;
    const float w0 = (1.0f - eA0) * T;  T *= sA0;
    const float w1 = (1.0f - eA1) * T;  T *= sA1;
    const float w2 = (1.0f - eA2) * T;  T *= sA2;
    const float w3 = (1.0f - eA3) * T;
    const float carry = __shfl_sync(FULL, inclA, 31);

    float dacc = fmaf(w0, dA.x, fmaf(w1, dA.y, fmaf(w2, dA.z, w3 * dA.w)));
    float aacc = (w0 + w1) + (w2 + w3);

    // ---- 4) chunk B: 2 survivals, scan seeded by carry ----
    const float gsB0 = fmaxf(gB.x, 0.f) * NLOG2E;
    const float gsB1 = fmaxf(gB.y, 0.f) * NLOG2E;
    const float eB0 = ex2_approx(gsB0 * (dB.y - dB.x));
    const float delB1 = (lane == 31) ? BOARDER : (ndB - dB.y);
    const float eB1 = ex2_approx(gsB1 * delB1);
    const float sB0 = eB0 + EPS, sB1 = eB1 + EPS;

    float inclB = sB0 * sB1;
    #pragma unroll
    for (int off = 1; off < 32; off <<= 1) {
        const float v = __shfl_up_sync(FULL, inclB, off);
        if (lane >= off) inclB *= v;
    }
    float exclB = __shfl_up_sync(FULL, inclB, 1);
    if (lane == 0) exclB = 1.0f;

    const float TB  = carry * exclB;
    const float wB0 = (1.0f - eB0) * TB;
    const float wB1 = (1.0f - eB1) * (TB * sB0);

    dacc = fmaf(wB0, dB.x, fmaf(wB1, dB.y, dacc));
    aacc += wB0 + wB1;

    // ---- 5) weights: direct coalesced stores ----
    float* __restrict__ wbase = out + (size_t)NRAYS * 5 + (size_t)ray * NSAMP;
    __stcs((float4*)wbase + lane, make_float4(w0, w1, w2, w3));
    __stcs((float2*)(wbase + 128) + lane, make_float2(wB0, wB1));

    // ---- 6) rgb consume: lane reads its OWN samples from smem ----
    asm volatile("cp.async.wait_group 0;\n" ::: "memory");
    __syncwarp();

    const float* rr = &srgb[wid][0];
    // samples 4l..4l+3 -> floats 12l..12l+11 (16B aligned)
    const float4 rA0 = *(const float4*)(rr + 12 * lane);      // r0 g0 b0 r1
    const float4 rA1 = *(const float4*)(rr + 12 * lane + 4);  // g1 b1 r2 g2
    const float4 rA2 = *(const float4*)(rr + 12 * lane + 8);  // b2 r3 g3 b3
    // samples 128+2l, 128+2l+1 -> floats 384+6l..+5 (8B aligned)
    const float2 rB0 = *(const float2*)(rr + 384 + 6 * lane);     // r0 g0
    const float2 rB1 = *(const float2*)(rr + 384 + 6 * lane + 2); // b0 r1
    const float2 rB2 = *(const float2*)(rr + 384 + 6 * lane + 4); // g1 b1

    float c0, c1, c2;
    c0 = fmaf(w0, sigmoid_fast(rA0.x),
         fmaf(w1, sigmoid_fast(rA0.w),
         fmaf(w2, sigmoid_fast(rA1.z),
              w3 * sigmoid_fast(rA2.y))));
    c1 = fmaf(w0, sigmoid_fast(rA0.y),
         fmaf(w1, sigmoid_fast(rA1.x),
         fmaf(w2, sigmoid_fast(rA1.w),
              w3 * sigmoid_fast(rA2.z))));
    c2 = fmaf(w0, sigmoid_fast(rA0.z),
         fmaf(w1, sigmoid_fast(rA1.y),
         fmaf(w2, sigmoid_fast(rA2.x),
              w3 * sigmoid_fast(rA2.w))));
    c0 = fmaf(wB0, sigmoid_fast(rB0.x), fmaf(wB1, sigmoid_fast(rB1.y), c0));
    c1 = fmaf(wB0, sigmoid_fast(rB0.y), fmaf(wB1, sigmoid_fast(rB2.x), c1));
    c2 = fmaf(wB0, sigmoid_fast(rB1.x), fmaf(wB1, sigmoid_fast(rB2.y), c2));

    // ---- 7) warp reduction + per-ray outputs ----
    #pragma unroll
    for (int off = 16; off > 0; off >>= 1) {
        c0   += __shfl_down_sync(FULL, c0,   off);
        c1   += __shfl_down_sync(FULL, c1,   off);
        c2   += __shfl_down_sync(FULL, c2,   off);
        dacc += __shfl_down_sync(FULL, dacc, off);
        aacc += __shfl_down_sync(FULL, aacc, off);
    }
    if (lane == 0) {
        out[3 * ray + 0] = c0;
        out[3 * ray + 1] = c1;
        out[3 * ray + 2] = c2;
        out[(size_t)NRAYS * 3 + ray] = dacc;
        out[(size_t)NRAYS * 4 + ray] = aacc;
    }
}

extern "C" void kernel_launch(void* const* d_in, const int* in_sizes, int n_in,
                              void* d_out, int out_size)
{
    const float* depth = (const float*)d_in[0];
    const float* rgb   = (const float*)d_in[1];
    const float* sigma = (const float*)d_in[2];
    float* out = (float*)d_out;

    const int threads = 32 * WPB;               // 256
    const int blocks  = NRAYS / WPB;            // 8192
    volrend_kernel<<<blocks, threads>>>(depth, rgb, sigma, out);
}